// round 10
// baseline (speedup 1.0000x reference)
#include <cuda_runtime.h>
#include <cuda_fp16.h>
#include <math.h>

#define Natoms 1024
#define Hdim   256
#define Ldim   512
#define NGs    50
#define NIs    3
#define Bmol   16
#define NGRID  384
#define CUT    5.0f
#define TR     16
#define WIN    11

#define A_PAD 264
#define W_PAD 72
#define GEMM_SMEM (32*A_PAD*2 + 256*W_PAD*2)
#define AGG_SMEM (NGRID*Hdim*2 + 8*256*4)
#define MLP_SMEM ((16*264 + 16*264 + 256*264)*2)   // A + T + W = 152064 B

typedef unsigned long long ull;

// scratch (no allocations allowed)
__device__ float  g_h[Natoms*Hdim];
__device__ __align__(16) __half g_hh[Natoms*Hdim];
__device__ __align__(16) __half g_aggh[Natoms*Hdim];
__device__ __align__(16) __half g_Gh[NIs*NGRID*Hdim];
__device__ __align__(16) __half g_tab[NIs*NGRID*Hdim];
__device__ __align__(16) __half g_fw2h[NIs*Hdim*Hdim];
__device__ __align__(16) __half g_aw1h[NIs*Hdim*Hdim];
__device__ __align__(16) __half g_aw2h[NIs*Hdim*Hdim];
__device__ float  g_pool[Bmol*Hdim];
__device__ unsigned g_nbr[Natoms*Natoms];
__device__ int      g_cnt[Natoms];

__device__ __forceinline__ float gelu_f(float x){
    return 0.5f*x*(1.0f+erff(x*0.70710678118654752f));
}
__device__ __forceinline__ unsigned smem_u32(const void* p){
    return (unsigned)__cvta_generic_to_shared(p);
}
__device__ __forceinline__ void ldsm_x4(unsigned& r0,unsigned& r1,unsigned& r2,unsigned& r3,unsigned addr){
    asm volatile("ldmatrix.sync.aligned.m8n8.x4.shared.b16 {%0,%1,%2,%3}, [%4];"
        : "=r"(r0),"=r"(r1),"=r"(r2),"=r"(r3) : "r"(addr));
}
__device__ __forceinline__ void ldsm_x4t(unsigned& r0,unsigned& r1,unsigned& r2,unsigned& r3,unsigned addr){
    asm volatile("ldmatrix.sync.aligned.m8n8.x4.trans.shared.b16 {%0,%1,%2,%3}, [%4];"
        : "=r"(r0),"=r"(r1),"=r"(r2),"=r"(r3) : "r"(addr));
}
__device__ __forceinline__ void hmma(float* c, unsigned a0,unsigned a1,unsigned a2,unsigned a3,
                                     unsigned b0,unsigned b1){
    asm volatile("mma.sync.aligned.m16n8k16.row.col.f32.f16.f16.f32 "
        "{%0,%1,%2,%3}, {%4,%5,%6,%7}, {%8,%9}, {%0,%1,%2,%3};"
        : "+f"(c[0]),"+f"(c[1]),"+f"(c[2]),"+f"(c[3])
        : "r"(a0),"r"(a1),"r"(a2),"r"(a3),"r"(b0),"r"(b1));
}

// ---------------- mega prep: nbr | embed | weight-cvt | pool-zero | hidden
// grid layout: [0,1024) nbr, [1024,2048) embed, [2048,2816) cvt,
//              [2816,2832) pool0, [2832,2904) hidden
__global__ void k_mega(const int* __restrict__ z, const float* __restrict__ emb,
                       const float* __restrict__ fw2, const float* __restrict__ aw1,
                       const float* __restrict__ aw2, const float* __restrict__ pos,
                       const float* __restrict__ fw1all, const float* __restrict__ fb1all){
    __shared__ int warp_cnt[8];
    __shared__ float rbf[TR][WIN+1];
    __shared__ int s_base;
    int b=blockIdx.x, tid=threadIdx.x;

    if(b<Natoms){
        // ---------------- neighbor list for atom b
        int i=b;
        float xi=pos[i*3+0], yi=pos[i*3+1], zi=pos[i*3+2];
        const float scale=(float)(NGRID-1)/CUT;
        int total=0;
        for(int base=0;base<Natoms;base+=256){
            int j=base+tid;
            float dx=pos[j*3+0]-xi;
            float dy=pos[j*3+1]-yi;
            float dz=pos[j*3+2]-zi;
            float d=sqrtf(dx*dx+dy*dy+dz*dz);
            bool keep=(j!=i)&&(d<CUT)&&(d>1e-6f);
            unsigned m=__ballot_sync(0xffffffffu,keep);
            if((tid&31)==0) warp_cnt[tid>>5]=__popc(m);
            __syncthreads();
            int off=total;
            int w=tid>>5;
            for(int ww=0;ww<w;ww++) off+=warp_cnt[ww];
            if(keep){
                int p=off+__popc(m&((1u<<(tid&31))-1u));
                float t=d*scale;
                int r=(int)(t+0.5f);
                if(r<1)r=1; if(r>NGRID-2)r=NGRID-2;
                float f=t-(float)r;
                int fq=(int)((f+1.0f)*4096.0f);
                if(fq<0)fq=0; if(fq>8191)fq=8191;
                g_nbr[i*Natoms+p]=(unsigned)j | ((unsigned)r<<10) | ((unsigned)fq<<19);
            }
            int bt=0;
            #pragma unroll
            for(int ww=0;ww<8;ww++) bt+=warp_cnt[ww];
            total+=bt;
            __syncthreads();
        }
        if(tid==0) g_cnt[i]=total;
    }else if(b<2*Natoms){
        // ---------------- embedding
        int i=b-Natoms;
        float v=emb[z[i]*Hdim+tid];
        g_h[i*Hdim+tid]=v;
        g_hh[i*Hdim+tid]=__float2half(v);
    }else if(b<2*Natoms+768){
        // ---------------- weight fp16 conversion
        int idx=(b-2*Natoms)*256+tid;
        g_fw2h[idx]=__float2half(fw2[idx]);
        g_aw1h[idx]=__float2half(aw1[idx]);
        g_aw2h[idx]=__float2half(aw2[idx]);
    }else if(b<2*Natoms+768+16){
        // ---------------- pool zero
        int idx=(b-2*Natoms-768)*256+tid;
        g_pool[idx]=0.f;
    }else{
        // ---------------- table hidden: G = gelu(rbf @ fw1 + fb1)
        int hb=b-(2*Natoms+768+16);
        int layer=hb/24;
        int r0=(hb%24)*TR;
        const float* fw1=fw1all+layer*NGs*Hdim;
        const float* fb1=fb1all+layer*Hdim;
        int c=tid;
        const float dstep  = CUT/(float)(NGRID-1);
        const float cstep  = CUT/(float)(NGs-1);
        const float inv2w2 = 1.0f/(2.0f*0.05f*0.05f);
        if(c==0){
            float dmid=((float)r0+7.5f)*dstep;
            s_base=(int)(dmid/cstep+0.5f)-(WIN/2);
        }
        __syncthreads();
        int base=s_base;
        for(int t=c;t<TR*WIN;t+=256){
            int row=t/WIN, g=t%WIN;
            int gi=base+g;
            float d=(float)(r0+row)*dstep;
            float u=d-(float)gi*cstep;
            float v=expf(-u*u*inv2w2);
            rbf[row][g]=(gi>=0 && gi<NGs)?v:0.0f;
        }
        __syncthreads();
        float acc[TR];
        float b1=fb1[c];
        #pragma unroll
        for(int t=0;t<TR;t++) acc[t]=b1;
        #pragma unroll
        for(int g=0;g<WIN;g++){
            int gi=base+g;
            gi=(gi<0)?0:((gi>NGs-1)?NGs-1:gi);
            float w=fw1[gi*Hdim+c];
            #pragma unroll
            for(int t=0;t<TR;t++) acc[t]=fmaf(rbf[t][g],w,acc[t]);
        }
        __half* G=g_Gh+layer*NGRID*Hdim;
        #pragma unroll
        for(int t=0;t<TR;t++) G[(r0+t)*Hdim+c]=__float2half(gelu_f(acc[t]));
    }
}

// --------------------------- tensor-core GEMM for the table (unchanged)
__global__ void __launch_bounds__(256) k_tgemm(const __half* __restrict__ A,
                       const __half* __restrict__ W16,
                       const float* __restrict__ bias,
                       __half* __restrict__ Ch){
    extern __shared__ __align__(16) __half sm[];
    __half* As=sm;
    __half* Ws=sm+32*A_PAD;
    int L=blockIdx.z;
    A   += (size_t)L*NGRID*Hdim;
    W16 += (size_t)L*Hdim*Hdim;
    bias+= (size_t)L*Hdim;
    Ch  += (size_t)L*NGRID*Hdim;
    int m0=blockIdx.x*32, n0=blockIdx.y*64;
    int tid=threadIdx.x;
    int wid=tid>>5, lane=tid&31;
    int wm=wid&1, wn=wid>>1;
    {
        int ar=tid>>3, ac=(tid&7)*8;
        #pragma unroll
        for(int p=0;p<4;p++){
            *reinterpret_cast<uint4*>(&As[ar*A_PAD + p*64 + ac]) =
                *reinterpret_cast<const uint4*>(&A[(size_t)(m0+ar)*Hdim + p*64 + ac]);
        }
        const __half* wrow=&W16[(size_t)tid*Hdim + n0];
        __half* srow=&Ws[tid*W_PAD];
        #pragma unroll
        for(int c=0;c<8;c++){
            *reinterpret_cast<uint4*>(&srow[c*8]) =
                *reinterpret_cast<const uint4*>(&wrow[c*8]);
        }
    }
    __syncthreads();
    float acc[2][4];
    #pragma unroll
    for(int nb=0;nb<2;nb++)
        #pragma unroll
        for(int q=0;q<4;q++) acc[nb][q]=0.f;
    unsigned a_base=smem_u32(&As[(wm*16 + (lane&7) + ((lane>>3)&1)*8)*A_PAD + ((lane>>4)&1)*8]);
    unsigned b_base=smem_u32(&Ws[((lane&7) + ((lane>>3)&1)*8)*W_PAD + wn*16 + ((lane>>4)&1)*8]);
    #pragma unroll
    for(int kc=0;kc<16;kc++){
        unsigned a0,a1,a2,a3, b0,b1,b2,b3;
        ldsm_x4 (a0,a1,a2,a3, a_base + kc*16*2);
        ldsm_x4t(b0,b1,b2,b3, b_base + kc*16*W_PAD*2);
        hmma(acc[0],a0,a1,a2,a3,b0,b1);
        hmma(acc[1],a0,a1,a2,a3,b2,b3);
    }
    int row0=m0 + wm*16 + (lane>>2);
    int row1=row0+8;
    #pragma unroll
    for(int nb=0;nb<2;nb++){
        int col=n0 + wn*16 + nb*8 + (lane&3)*2;
        float bz0=bias[col], bz1=bias[col+1];
        *reinterpret_cast<__half2*>(&Ch[(size_t)row0*Hdim+col])=__floats2half2_rn(acc[nb][0]+bz0,acc[nb][1]+bz1);
        *reinterpret_cast<__half2*>(&Ch[(size_t)row1*Hdim+col])=__floats2half2_rn(acc[nb][2]+bz0,acc[nb][3]+bz1);
    }
}

// --------------------------- fused per-layer MLP:
// h += gelu(agg@W1+b1)@W2 + b2 ; optional pool atomics.
// 64 CTAs x 16 rows; W (128KB) fully smem-resident per stage; barrier-free gemms.
template<bool POOL>
__global__ void __launch_bounds__(256) k_mlp(const __half* __restrict__ W1,
                       const __half* __restrict__ W2,
                       const float* __restrict__ b1v, const float* __restrict__ b2v,
                       const int* __restrict__ batch){
    extern __shared__ __align__(16) __half sm[];
    __half* As=sm;                // [16][264]
    __half* Ts=sm+16*264;         // [16][264]
    __half* Ws=sm+32*264;         // [256][264]
    int tid=threadIdx.x, lane=tid&31, wid=tid>>5;
    int m0=blockIdx.x*16;
    int n0w=wid*32;

    // load A (agg, fp16) 16x256
    {
        int r=tid>>4, c=(tid&15)*16;
        *reinterpret_cast<uint4*>(&As[r*264+c  ]) =
            *reinterpret_cast<const uint4*>(&g_aggh[(size_t)(m0+r)*Hdim+c  ]);
        *reinterpret_cast<uint4*>(&As[r*264+c+8]) =
            *reinterpret_cast<const uint4*>(&g_aggh[(size_t)(m0+r)*Hdim+c+8]);
    }
    // load W1 (row tid)
    {
        const uint4* src=reinterpret_cast<const uint4*>(&W1[(size_t)tid*Hdim]);
        #pragma unroll
        for(int c=0;c<32;c++)
            *reinterpret_cast<uint4*>(&Ws[tid*264+c*8])=src[c];
    }
    __syncthreads();

    unsigned lrow=(lane&7)+((lane>>3)&1)*8;
    unsigned lcol=((lane>>4)&1)*8;
    unsigned aA=smem_u32(&As[lrow*264 + lcol]);
    unsigned aT=smem_u32(&Ts[lrow*264 + lcol]);
    unsigned aW=smem_u32(&Ws[lrow*264 + n0w + lcol]);

    // ---- gemm1
    float acc1[4][4];
    #pragma unroll
    for(int i=0;i<4;i++)
        #pragma unroll
        for(int q=0;q<4;q++) acc1[i][q]=0.f;
    #pragma unroll
    for(int kc=0;kc<16;kc++){
        unsigned a0,a1,a2,a3;
        ldsm_x4(a0,a1,a2,a3, aA + kc*32);
        #pragma unroll
        for(int blk=0;blk<2;blk++){
            unsigned b0,b1,b2,b3;
            ldsm_x4t(b0,b1,b2,b3, aW + (kc*16*264 + blk*16)*2);
            hmma(acc1[blk*2+0],a0,a1,a2,a3,b0,b1);
            hmma(acc1[blk*2+1],a0,a1,a2,a3,b2,b3);
        }
    }
    // epilogue 1: gelu -> Ts
    {
        int r0=lane>>2;
        #pragma unroll
        for(int blk=0;blk<2;blk++)
            #pragma unroll
            for(int nb=0;nb<2;nb++){
                int col=n0w+blk*16+nb*8+(lane&3)*2;
                float* a=acc1[blk*2+nb];
                float x0=gelu_f(a[0]+b1v[col]);
                float x1=gelu_f(a[1]+b1v[col+1]);
                float x2=gelu_f(a[2]+b1v[col]);
                float x3=gelu_f(a[3]+b1v[col+1]);
                *reinterpret_cast<__half2*>(&Ts[r0*264+col])    =__floats2half2_rn(x0,x1);
                *reinterpret_cast<__half2*>(&Ts[(r0+8)*264+col])=__floats2half2_rn(x2,x3);
            }
    }
    __syncthreads();
    // load W2 over W1
    {
        const uint4* src=reinterpret_cast<const uint4*>(&W2[(size_t)tid*Hdim]);
        #pragma unroll
        for(int c=0;c<32;c++)
            *reinterpret_cast<uint4*>(&Ws[tid*264+c*8])=src[c];
    }
    __syncthreads();

    // ---- gemm2
    float acc2[4][4];
    #pragma unroll
    for(int i=0;i<4;i++)
        #pragma unroll
        for(int q=0;q<4;q++) acc2[i][q]=0.f;
    #pragma unroll
    for(int kc=0;kc<16;kc++){
        unsigned a0,a1,a2,a3;
        ldsm_x4(a0,a1,a2,a3, aT + kc*32);
        #pragma unroll
        for(int blk=0;blk<2;blk++){
            unsigned b0,b1,b2,b3;
            ldsm_x4t(b0,b1,b2,b3, aW + (kc*16*264 + blk*16)*2);
            hmma(acc2[blk*2+0],a0,a1,a2,a3,b0,b1);
            hmma(acc2[blk*2+1],a0,a1,a2,a3,b2,b3);
        }
    }
    // epilogue 2: +bias +residual -> g_h, g_hh (+pool)
    {
        int row0=m0+(lane>>2), row1=row0+8;
        #pragma unroll
        for(int blk=0;blk<2;blk++)
            #pragma unroll
            for(int nb=0;nb<2;nb++){
                int col=n0w+blk*16+nb*8+(lane&3)*2;
                float* a=acc2[blk*2+nb];
                float bz0=b2v[col], bz1=b2v[col+1];
                float x00=a[0]+bz0+g_h[(size_t)row0*Hdim+col];
                float x01=a[1]+bz1+g_h[(size_t)row0*Hdim+col+1];
                float x10=a[2]+bz0+g_h[(size_t)row1*Hdim+col];
                float x11=a[3]+bz1+g_h[(size_t)row1*Hdim+col+1];
                *reinterpret_cast<float2*>(&g_h[(size_t)row0*Hdim+col])=make_float2(x00,x01);
                *reinterpret_cast<float2*>(&g_h[(size_t)row1*Hdim+col])=make_float2(x10,x11);
                *reinterpret_cast<__half2*>(&g_hh[(size_t)row0*Hdim+col])=__floats2half2_rn(x00,x01);
                *reinterpret_cast<__half2*>(&g_hh[(size_t)row1*Hdim+col])=__floats2half2_rn(x10,x11);
                if(POOL){
                    int br0=batch[row0], br1=batch[row1];
                    atomicAdd(&g_pool[br0*Hdim+col  ],x00);
                    atomicAdd(&g_pool[br0*Hdim+col+1],x01);
                    atomicAdd(&g_pool[br1*Hdim+col  ],x10);
                    atomicAdd(&g_pool[br1*Hdim+col+1],x11);
                }
            }
    }
}

// ------------------- neighbor aggregation (proven v3)
__device__ __forceinline__ void agg_step4(unsigned p, uint2 hv,
                                          const __half2* __restrict__ tab_s,
                                          int c2, float2& a0, float2& a1){
    int r=(p>>10)&511;
    float f=(float)(p>>19)*(1.0f/4096.0f)-1.0f;
    float f2=f*f;
    __half2 al=__float2half2_rn(0.5f*(f2+f));
    __half2 be=__float2half2_rn(1.0f-f2);
    __half2 ga=__float2half2_rn(0.5f*(f2-f));
    const __half2* base=tab_s + r*128 + c2;
    uint2 mu=*reinterpret_cast<const uint2*>(base-128);
    uint2 zu=*reinterpret_cast<const uint2*>(base);
    uint2 qu=*reinterpret_cast<const uint2*>(base+128);
    __half2 m0=*reinterpret_cast<__half2*>(&mu.x), m1=*reinterpret_cast<__half2*>(&mu.y);
    __half2 z0=*reinterpret_cast<__half2*>(&zu.x), z1=*reinterpret_cast<__half2*>(&zu.y);
    __half2 q0=*reinterpret_cast<__half2*>(&qu.x), q1=*reinterpret_cast<__half2*>(&qu.y);
    __half2 h0=*reinterpret_cast<__half2*>(&hv.x), h1=*reinterpret_cast<__half2*>(&hv.y);
    __half2 w0=__hfma2(al,q0,__hfma2(be,z0,__hmul2(ga,m0)));
    __half2 w1=__hfma2(al,q1,__hfma2(be,z1,__hmul2(ga,m1)));
    float2 p0=__half22float2(__hmul2(w0,h0));
    float2 p1=__half22float2(__hmul2(w1,h1));
    a0.x+=p0.x; a0.y+=p0.y;
    a1.x+=p1.x; a1.y+=p1.y;
}

__global__ void __launch_bounds__(512,1) k_agg(const __half2* __restrict__ tab){
    extern __shared__ __half2 tab_s[];
    float* red=reinterpret_cast<float*>(tab_s + NGRID*128);
    int tid=threadIdx.x;
    {
        const uint4* src=reinterpret_cast<const uint4*>(tab);
        uint4* dst=reinterpret_cast<uint4*>(tab_s);
        #pragma unroll
        for(int idx=tid;idx<(NGRID*Hdim*2)/16;idx+=512) dst[idx]=src[idx];
    }
    __syncthreads();
    int strip=tid>>6;
    int c4=tid&63;
    int c2=c4*2;
    const uint2* __restrict__ hh=reinterpret_cast<const uint2*>(g_hh);
    for(int a=0;a<8;a++){
        int i=blockIdx.x*8+a;
        int total=g_cnt[i];
        const unsigned* __restrict__ lst=g_nbr+i*Natoms;
        int n0=(total*strip)>>3;
        int n1=(total*(strip+1))>>3;
        float2 a0=make_float2(0.f,0.f), a1=make_float2(0.f,0.f);
        int n=n0;
        for(; n+4<=n1; n+=4){
            unsigned p0=__ldg(lst+n+0);
            unsigned p1=__ldg(lst+n+1);
            unsigned p2=__ldg(lst+n+2);
            unsigned p3=__ldg(lst+n+3);
            uint2 h0=__ldg(hh+(p0&1023)*64+c4);
            uint2 h1=__ldg(hh+(p1&1023)*64+c4);
            uint2 h2=__ldg(hh+(p2&1023)*64+c4);
            uint2 h3=__ldg(hh+(p3&1023)*64+c4);
            agg_step4(p0,h0,tab_s,c2,a0,a1);
            agg_step4(p1,h1,tab_s,c2,a0,a1);
            agg_step4(p2,h2,tab_s,c2,a0,a1);
            agg_step4(p3,h3,tab_s,c2,a0,a1);
        }
        for(; n<n1; n++){
            unsigned p=__ldg(lst+n);
            uint2 hv=__ldg(hh+(p&1023)*64+c4);
            agg_step4(p,hv,tab_s,c2,a0,a1);
        }
        float4 v=make_float4(a0.x,a0.y,a1.x,a1.y);
        *reinterpret_cast<float4*>(&red[strip*256 + c4*4])=v;
        __syncthreads();
        if(tid<128){
            float s0=0.f, s1=0.f;
            #pragma unroll
            for(int s=0;s<8;s++){
                float2 t=*reinterpret_cast<const float2*>(&red[s*256 + tid*2]);
                s0+=t.x; s1+=t.y;
            }
            reinterpret_cast<__half2*>(g_aggh)[i*128+tid]=__floats2half2_rn(s0,s1);
        }
        __syncthreads();
    }
}

// ------------------------------------------------- projection head + layernorm
__global__ void __launch_bounds__(512) k_head(
                       const float* __restrict__ pw1,const float* __restrict__ pb1,
                       const float* __restrict__ pw2,const float* __restrict__ pb2,
                       const float* __restrict__ lng,const float* __restrict__ lnb,
                       float* __restrict__ out){
    __shared__ float pv[Hdim];
    __shared__ float tv[Hdim];
    __shared__ float red[16];
    __shared__ float s_mu, s_inv;
    int b=blockIdx.x, tid=threadIdx.x;
    if(tid<Hdim) pv[tid]=g_pool[b*Hdim+tid];
    __syncthreads();
    if(tid<Hdim){
        float a=pb1[tid];
        for(int k=0;k<Hdim;k++) a=fmaf(pv[k],pw1[k*Hdim+tid],a);
        tv[tid]=gelu_f(a);
    }
    __syncthreads();
    float x=pb2[tid];
    for(int k=0;k<Hdim;k++) x=fmaf(tv[k],pw2[k*Ldim+tid],x);
    float sv=x;
    for(int d=16;d>0;d>>=1) sv+=__shfl_down_sync(0xffffffffu,sv,d);
    if((tid&31)==0) red[tid>>5]=sv;
    __syncthreads();
    if(tid==0){
        float t=0.f;
        #pragma unroll
        for(int w=0;w<16;w++) t+=red[w];
        s_mu=t/(float)Ldim;
    }
    __syncthreads();
    float mu=s_mu;
    float dv=x-mu;
    float s2=dv*dv;
    for(int d=16;d>0;d>>=1) s2+=__shfl_down_sync(0xffffffffu,s2,d);
    if((tid&31)==0) red[tid>>5]=s2;
    __syncthreads();
    if(tid==0){
        float t=0.f;
        #pragma unroll
        for(int w=0;w<16;w++) t+=red[w];
        s_inv=1.0f/sqrtf(t/(float)Ldim + 1e-5f);
    }
    __syncthreads();
    out[b*Ldim+tid]=(x-mu)*s_inv*lng[tid]+lnb[tid];
}

// ------------------------------------------------------------------ launcher
extern "C" void kernel_launch(void* const* d_in, const int* in_sizes, int n_in,
                              void* d_out, int out_size){
    const int*   z    =(const int*)  d_in[0];
    const float* pos  =(const float*)d_in[1];
    const int*   batch=(const int*)  d_in[2];
    const float* emb  =(const float*)d_in[3];
    const float* fw1  =(const float*)d_in[4];
    const float* fb1  =(const float*)d_in[5];
    const float* fw2  =(const float*)d_in[6];
    const float* fb2  =(const float*)d_in[7];
    const float* aw1  =(const float*)d_in[8];
    const float* ab1  =(const float*)d_in[9];
    const float* aw2  =(const float*)d_in[10];
    const float* ab2  =(const float*)d_in[11];
    const float* pw1  =(const float*)d_in[12];
    const float* pb1  =(const float*)d_in[13];
    const float* pw2  =(const float*)d_in[14];
    const float* pb2  =(const float*)d_in[15];
    const float* lng  =(const float*)d_in[16];
    const float* lnb  =(const float*)d_in[17];
    float* out=(float*)d_out;

    __half *ptab,*pGh,*pfw2h,*paw1h,*paw2h;
    cudaGetSymbolAddress((void**)&ptab, g_tab);
    cudaGetSymbolAddress((void**)&pGh,  g_Gh);
    cudaGetSymbolAddress((void**)&pfw2h,g_fw2h);
    cudaGetSymbolAddress((void**)&paw1h,g_aw1h);
    cudaGetSymbolAddress((void**)&paw2h,g_aw2h);

    cudaFuncSetAttribute(k_agg, cudaFuncAttributeMaxDynamicSharedMemorySize, AGG_SMEM);
    cudaFuncSetAttribute(k_tgemm, cudaFuncAttributeMaxDynamicSharedMemorySize, GEMM_SMEM);
    cudaFuncSetAttribute((const void*)k_mlp<false>, cudaFuncAttributeMaxDynamicSharedMemorySize, MLP_SMEM);
    cudaFuncSetAttribute((const void*)k_mlp<true >, cudaFuncAttributeMaxDynamicSharedMemorySize, MLP_SMEM);

    k_mega<<<2*Natoms+768+16+72,256>>>(z,emb,fw2,aw1,aw2,pos,fw1,fb1);
    k_tgemm<<<dim3(NGRID/32,Hdim/64,NIs),256,GEMM_SMEM>>>(pGh, pfw2h, fb2, ptab);
    for(int l=0;l<NIs;l++){
        k_agg<<<Natoms/8,512,AGG_SMEM>>>(reinterpret_cast<const __half2*>(ptab)+(size_t)l*NGRID*Hdim/2);
        if(l<NIs-1)
            k_mlp<false><<<Natoms/16,256,MLP_SMEM>>>(paw1h+(size_t)l*Hdim*Hdim, paw2h+(size_t)l*Hdim*Hdim,
                                                     ab1+l*Hdim, ab2+l*Hdim, batch);
        else
            k_mlp<true ><<<Natoms/16,256,MLP_SMEM>>>(paw1h+(size_t)l*Hdim*Hdim, paw2h+(size_t)l*Hdim*Hdim,
                                                     ab1+l*Hdim, ab2+l*Hdim, batch);
    }
    k_head<<<Bmol,512>>>(pw1,pb1,pw2,pb2,lng,lnb,out);
}